// round 16
// baseline (speedup 1.0000x reference)
#include <cuda_runtime.h>
#include <cuda_bf16.h>
#include <cstdint>

#define NVOX  40000
#define BEVH  496
#define BEVW  432
#define NCELL (BEVH*BEVW)
#define CAP   32
#define EPSF  1e-5f

typedef unsigned long long ull;

__device__ float g_voxelwise[NVOX * 64];
__device__ int   g_cellCount[NCELL];
__device__ int   g_cellMem[NCELL * CAP];
__device__ int   g_workCell[NVOX];
__device__ int   g_workNumv[NVOX];
__device__ int   g_workMem[NVOX * 16];
__device__ int   g_workCount;

__device__ __forceinline__ ull pk(float x, float y) {
    ull r; asm("mov.b64 %0,{%1,%2};" : "=l"(r) : "f"(x), "f"(y)); return r;
}
__device__ __forceinline__ float hsum(ull v) {
    float a, b; asm("mov.b64 {%0,%1},%2;" : "=f"(a), "=f"(b) : "l"(v)); return a + b;
}
__device__ __forceinline__ ull ffma2(ull a, ull b, ull c) {
    ull d; asm("fma.rn.f32x2 %0,%1,%2,%3;" : "=l"(d) : "l"(a), "l"(b), "l"(c)); return d;
}
__device__ __forceinline__ float mish(float y) {
    float u = __expf(fminf(y, 25.0f));
    float t = 1.0f + u;
    t = t * t;
    return y * __fdividef(t - 1.0f, t + 1.0f);
}
__device__ __forceinline__ uint32_t smem_u32(const void* p) {
    uint32_t a;
    asm("{ .reg .u64 t; cvta.to.shared.u64 t, %1; cvt.u32.u64 %0, t; }" : "=r"(a) : "l"(p));
    return a;
}
// fast hi/lo bf16 split: hi = pack(bf16(x1), bf16(x0)); residuals via bit-mask extract
__device__ __forceinline__ void bfsplit(float x0, float x1, uint32_t& hu, uint32_t& lu) {
    uint32_t h;
    asm("cvt.rn.bf16x2.f32 %0, %1, %2;" : "=r"(h) : "f"(x1), "f"(x0));
    float h0 = __uint_as_float(h << 16);
    float h1 = __uint_as_float(h & 0xFFFF0000u);
    float r0 = x0 - h0, r1 = x1 - h1;
    asm("cvt.rn.bf16x2.f32 %0, %1, %2;" : "=r"(lu) : "f"(r1), "f"(r0));
    hu = h;
}

#define LDM_X4(r0, r1, r2, r3, addr) \
    asm volatile("ldmatrix.sync.aligned.m8n8.x4.shared.b16 {%0,%1,%2,%3}, [%4];" \
        : "=r"(r0), "=r"(r1), "=r"(r2), "=r"(r3) : "r"(addr))
#define LDM_X2(r0, r1, addr) \
    asm volatile("ldmatrix.sync.aligned.m8n8.x2.shared.b16 {%0,%1}, [%2];" \
        : "=r"(r0), "=r"(r1) : "r"(addr))
#define MMA16816(d, a0, a1, a2, a3, b0, b1) \
    asm volatile("mma.sync.aligned.m16n8k16.row.col.f32.bf16.bf16.f32 " \
        "{%0,%1,%2,%3},{%4,%5,%6,%7},{%8,%9},{%0,%1,%2,%3};" \
        : "+f"(d[0]), "+f"(d[1]), "+f"(d[2]), "+f"(d[3]) \
        : "r"(a0), "r"(a1), "r"(a2), "r"(a3), "r"(b0), "r"(b1))

__global__ void k_zero_out(float4* out, int n4) {
    int i = blockIdx.x * blockDim.x + threadIdx.x;
    int stride = gridDim.x * blockDim.x;
    float4 z = make_float4(0.f, 0.f, 0.f, 0.f);
    for (; i < n4; i += stride) out[i] = z;
}
__global__ void k_zero_meta() {
    int i = blockIdx.x * blockDim.x + threadIdx.x;
    if (i < NCELL) g_cellCount[i] = 0;
    if (i == 0) g_workCount = 0;
}

// ---------------- VFE via mma.sync: warp = voxel, 16 warps/CTA ----------------
#define SM_W1   0
#define SM_S1   256
#define SM_O1   288
#define SM_S2   320
#define SM_O2   448
#define SM_O3   576
#define SM_O4   832
#define SM_W2   1088
#define SM_W3H  3136
#define SM_W3L  12352
#define SM_W4H  21568
#define SM_W4L  30784
#define SM_A    40000
#define AWARP   9216
#define NW      16
#define VFE_SMEM (SM_A + NW * AWARP)   /* 187456 B */
#define NTILE   ((NVOX + NW - 1) / NW)

__global__ __launch_bounds__(32 * NW) void k_vfe(
    const float* __restrict__ feat, const int* __restrict__ nvox,
    const float* __restrict__ W1, const float* __restrict__ bn1,
    const float* __restrict__ W2, const float* __restrict__ bn2,
    const float* __restrict__ W3, const float* __restrict__ bn3,
    const float* __restrict__ W4, const float* __restrict__ bn4)
{
    extern __shared__ char smc[];
    const uint32_t sb = smem_u32(smc);
    float* W1s = (float*)(smc + SM_W1);
    float* s1s = (float*)(smc + SM_S1);
    float* o1s = (float*)(smc + SM_O1);
    float* s2s = (float*)(smc + SM_S2);
    float* o2s = (float*)(smc + SM_O2);
    float* o3s = (float*)(smc + SM_O3);
    float* o4s = (float*)(smc + SM_O4);
    float* W2s = (float*)(smc + SM_W2);

    const int tid = threadIdx.x;
    const int wid = tid >> 5;
    const int lane = tid & 31;

    if (tid < 64) W1s[tid] = W1[tid];
    if (tid < 8) {
        float s = bn1[tid] * rsqrtf(bn1[24 + tid] + EPSF);
        s1s[tid] = s;
        o1s[tid] = bn1[8 + tid] - bn1[16 + tid] * s;
    }
    if (tid < 32) {
        float s = bn2[tid] * rsqrtf(bn2[96 + tid] + EPSF);
        s2s[tid] = s;
        o2s[tid] = bn2[32 + tid] - bn2[64 + tid] * s;
    }
    if (tid < 64) {
        float s3 = bn3[tid] * rsqrtf(bn3[192 + tid] + EPSF);
        o3s[tid] = bn3[64 + tid] - bn3[128 + tid] * s3;
        float s4 = bn4[tid] * rsqrtf(bn4[192 + tid] + EPSF);
        o4s[tid] = bn4[64 + tid] - bn4[128 + tid] * s4;
    }
    for (int i = tid; i < 512; i += 32 * NW) W2s[i] = W2[i];
    if (tid < 128) {
        int c = tid & 63, k0 = (tid >> 6) * 32;
        float s3c = bn3[c] * rsqrtf(bn3[192 + c] + EPSF);
        float s4c = bn4[c] * rsqrtf(bn4[192 + c] + EPSF);
        for (int k = k0; k < k0 + 32; k++) {
            int off = c * 144 + k * 2;
            float w3 = W3[c * 64 + k] * s3c;
            __nv_bfloat16 h = __float2bfloat16(w3);
            *(__nv_bfloat16*)(smc + SM_W3H + off) = h;
            *(__nv_bfloat16*)(smc + SM_W3L + off) = __float2bfloat16(w3 - __bfloat162float(h));
            float w4 = W4[c * 64 + k] * s4c;
            __nv_bfloat16 h4 = __float2bfloat16(w4);
            *(__nv_bfloat16*)(smc + SM_W4H + off) = h4;
            *(__nv_bfloat16*)(smc + SM_W4L + off) = __float2bfloat16(w4 - __bfloat162float(h4));
        }
    }
    __syncthreads();

    const uint32_t x2hA = sb + SM_A + wid * AWARP;
    const uint32_t x2lA = x2hA + 4608;
    char* const x2hp = smc + (x2hA - sb);
    char* const x2lp = smc + (x2lA - sb);
    const uint32_t a_ro = (uint32_t)(lane & 15) * 144 + ((lane & 16) ? 16u : 0u);
    const uint32_t b_ro = (uint32_t)(lane & 7) * 144 + ((lane & 8) ? 16u : 0u);
    const int g = lane >> 2, t = lane & 3;

    for (int q = blockIdx.x; q < NTILE; q += gridDim.x) {
        const int v = q * NW + wid;
        if (v >= NVOX) continue;
        const int numv = __ldg(nvox + v);
        const bool valid = lane < numv;
        const bool deep = (numv > 16);

        float p1[8];
        {
            const float4* fv = (const float4*)(feat + (size_t)v * 256);
            float4 fa = __ldg(fv + lane * 2), fb = __ldg(fv + lane * 2 + 1);
            ull fx[4] = { pk(fa.x, fa.y), pk(fa.z, fa.w), pk(fb.x, fb.y), pk(fb.z, fb.w) };
#pragma unroll
            for (int c = 0; c < 8; c++) {
                const ull* wr = (const ull*)(W1s + c * 8);
                ull acc = ffma2(fx[0], wr[0], 0ull);
                acc = ffma2(fx[1], wr[1], acc);
                acc = ffma2(fx[2], wr[2], acc);
                acc = ffma2(fx[3], wr[3], acc);
                p1[c] = mish(fmaf(hsum(acc), s1s[c], o1s[c]));
            }
        }
        float ag[8];
#pragma unroll
        for (int c = 0; c < 8; c++) {
            float a = p1[c];
#pragma unroll
            for (int o = 16; o; o >>= 1) a = fmaxf(a, __shfl_xor_sync(~0u, a, o));
            ag[c] = a;
        }

        float p2[32];
        {
            ull xp[8];
#pragma unroll
            for (int i = 0; i < 4; i++) xp[i] = pk(p1[2*i], p1[2*i+1]);
#pragma unroll
            for (int i = 0; i < 4; i++) xp[4+i] = pk(ag[2*i], ag[2*i+1]);
#pragma unroll
            for (int c = 0; c < 32; c++) {
                const ull* wr = (const ull*)(W2s + c * 16);
                ull acc = ffma2(xp[0], wr[0], 0ull);
#pragma unroll
                for (int i = 1; i < 8; i++) acc = ffma2(xp[i], wr[i], acc);
                p2[c] = mish(fmaf(hsum(acc), s2s[c], o2s[c]));
            }
        }
        float a2[32];
#pragma unroll
        for (int c = 0; c < 32; c++) a2[c] = p2[c];
#pragma unroll
        for (int o = 16; o; o >>= 1)
#pragma unroll
            for (int c = 0; c < 32; c++) a2[c] = fmaxf(a2[c], __shfl_xor_sync(~0u, a2[c], o));

        {
            const float mv = valid ? 1.f : 0.f;
            char* rh = x2hp + lane * 144;
            char* rl = x2lp + lane * 144;
#pragma unroll
            for (int i = 0; i < 4; i++) {
                uint4 uh, ul;
                bfsplit(p2[8*i]*mv,   p2[8*i+1]*mv, uh.x, ul.x);
                bfsplit(p2[8*i+2]*mv, p2[8*i+3]*mv, uh.y, ul.y);
                bfsplit(p2[8*i+4]*mv, p2[8*i+5]*mv, uh.z, ul.z);
                bfsplit(p2[8*i+6]*mv, p2[8*i+7]*mv, uh.w, ul.w);
                *(uint4*)(rh + 16*i) = uh;
                *(uint4*)(rl + 16*i) = ul;
            }
#pragma unroll
            for (int i = 0; i < 4; i++) {
                uint4 uh, ul;
                bfsplit(a2[8*i]*mv,   a2[8*i+1]*mv, uh.x, ul.x);
                bfsplit(a2[8*i+2]*mv, a2[8*i+3]*mv, uh.y, ul.y);
                bfsplit(a2[8*i+4]*mv, a2[8*i+5]*mv, uh.z, ul.z);
                bfsplit(a2[8*i+6]*mv, a2[8*i+7]*mv, uh.w, ul.w);
                *(uint4*)(rh + 64 + 16*i) = uh;
                *(uint4*)(rl + 64 + 16*i) = ul;
            }
        }
        __syncwarp();

        // ---- stage 3: mt=1 skipped when numv <= 16 (rows 16-31 all masked) ----
        uint32_t f4h[2][4][4], f4l[2][4][4];
#pragma unroll
        for (int mt = 0; mt < 2; mt++) {
            if (mt == 0 || deep) {
                uint32_t fah[4][4], fal[4][4];
#pragma unroll
                for (int kb = 0; kb < 4; kb++) {
                    uint32_t ad = (uint32_t)(mt * 16 * 144 + kb * 32) + a_ro;
                    LDM_X4(fah[kb][0], fah[kb][1], fah[kb][2], fah[kb][3], x2hA + ad);
                    LDM_X4(fal[kb][0], fal[kb][1], fal[kb][2], fal[kb][3], x2lA + ad);
                }
                const int r0 = mt * 16 + g, r1 = r0 + 8;
                const bool va0 = r0 < numv, va1 = r1 < numv;
#pragma unroll
                for (int nt = 0; nt < 8; nt++) {
                    float d[4] = {0, 0, 0, 0};
#pragma unroll
                    for (int kb = 0; kb < 4; kb++) {
                        uint32_t bd = (uint32_t)(nt * 8 * 144 + kb * 32) + b_ro;
                        uint32_t bh0, bh1, bl0, bl1;
                        LDM_X2(bh0, bh1, sb + SM_W3H + bd);
                        LDM_X2(bl0, bl1, sb + SM_W3L + bd);
                        MMA16816(d, fah[kb][0], fah[kb][1], fah[kb][2], fah[kb][3], bh0, bh1);
                        MMA16816(d, fal[kb][0], fal[kb][1], fal[kb][2], fal[kb][3], bh0, bh1);
                        MMA16816(d, fah[kb][0], fah[kb][1], fah[kb][2], fah[kb][3], bl0, bl1);
                    }
                    int c0 = nt * 8 + 2 * t;
                    float oc0 = o3s[c0], oc1 = o3s[c0 + 1];
                    int kb4 = nt >> 1, ai = (nt & 1) * 2;
                    float y00 = va0 ? mish(d[0] + oc0) : 0.f;
                    float y01 = va0 ? mish(d[1] + oc1) : 0.f;
                    bfsplit(y00, y01, f4h[mt][kb4][ai], f4l[mt][kb4][ai]);
                    float y10 = va1 ? mish(d[2] + oc0) : 0.f;
                    float y11 = va1 ? mish(d[3] + oc1) : 0.f;
                    bfsplit(y10, y11, f4h[mt][kb4][ai + 1], f4l[mt][kb4][ai + 1]);
                }
            }
        }

        // ---- stage 4 ----
        if (deep) {
            const float vinit = (numv == 32) ? -3.0e38f : 0.f;
#pragma unroll
            for (int nt = 0; nt < 8; nt++) {
                float d0[4] = {0,0,0,0}, d1[4] = {0,0,0,0};
#pragma unroll
                for (int kb = 0; kb < 4; kb++) {
                    uint32_t bd = (uint32_t)(nt * 8 * 144 + kb * 32) + b_ro;
                    uint32_t bh0, bh1, bl0, bl1;
                    LDM_X2(bh0, bh1, sb + SM_W4H + bd);
                    LDM_X2(bl0, bl1, sb + SM_W4L + bd);
                    MMA16816(d0, f4h[0][kb][0], f4h[0][kb][1], f4h[0][kb][2], f4h[0][kb][3], bh0, bh1);
                    MMA16816(d0, f4l[0][kb][0], f4l[0][kb][1], f4l[0][kb][2], f4l[0][kb][3], bh0, bh1);
                    MMA16816(d0, f4h[0][kb][0], f4h[0][kb][1], f4h[0][kb][2], f4h[0][kb][3], bl0, bl1);
                    MMA16816(d1, f4h[1][kb][0], f4h[1][kb][1], f4h[1][kb][2], f4h[1][kb][3], bh0, bh1);
                    MMA16816(d1, f4l[1][kb][0], f4l[1][kb][1], f4l[1][kb][2], f4l[1][kb][3], bh0, bh1);
                    MMA16816(d1, f4h[1][kb][0], f4h[1][kb][1], f4h[1][kb][2], f4h[1][kb][3], bl0, bl1);
                }
                int c0 = nt * 8 + 2 * t;
                float oc0 = o4s[c0], oc1 = o4s[c0 + 1];
                int rows[4] = { g, g + 8, g + 16, g + 24 };
                float dv[4][2] = { {d0[0], d0[1]}, {d0[2], d0[3]}, {d1[0], d1[1]}, {d1[2], d1[3]} };
                float vm0 = vinit, vm1 = vinit;
#pragma unroll
                for (int r = 0; r < 4; r++) {
                    if (rows[r] < numv) {
                        int off = rows[r] * 144 + c0 * 2;
                        uint32_t hu = *(const uint32_t*)(x2hp + off);
                        uint32_t lu = *(const uint32_t*)(x2lp + off);
                        __nv_bfloat162 hb = *reinterpret_cast<__nv_bfloat162*>(&hu);
                        __nv_bfloat162 lb = *reinterpret_cast<__nv_bfloat162*>(&lu);
                        float x20 = __bfloat162float(hb.x) + __bfloat162float(lb.x);
                        float x21 = __bfloat162float(hb.y) + __bfloat162float(lb.y);
                        vm0 = fmaxf(vm0, mish(dv[r][0] + oc0) + x20);
                        vm1 = fmaxf(vm1, mish(dv[r][1] + oc1) + x21);
                    }
                }
#pragma unroll
                for (int o = 4; o <= 16; o <<= 1) {
                    vm0 = fmaxf(vm0, __shfl_xor_sync(~0u, vm0, o));
                    vm1 = fmaxf(vm1, __shfl_xor_sync(~0u, vm1, o));
                }
                if (lane < 4) {
                    g_voxelwise[(size_t)v * 64 + nt * 8 + 2 * lane]     = vm0;
                    g_voxelwise[(size_t)v * 64 + nt * 8 + 2 * lane + 1] = vm1;
                }
            }
        } else {
            // shallow: rows 16-31 all masked -> d1 half skipped entirely
#pragma unroll
            for (int nt = 0; nt < 8; nt++) {
                float d0[4] = {0,0,0,0};
#pragma unroll
                for (int kb = 0; kb < 4; kb++) {
                    uint32_t bd = (uint32_t)(nt * 8 * 144 + kb * 32) + b_ro;
                    uint32_t bh0, bh1, bl0, bl1;
                    LDM_X2(bh0, bh1, sb + SM_W4H + bd);
                    LDM_X2(bl0, bl1, sb + SM_W4L + bd);
                    MMA16816(d0, f4h[0][kb][0], f4h[0][kb][1], f4h[0][kb][2], f4h[0][kb][3], bh0, bh1);
                    MMA16816(d0, f4l[0][kb][0], f4l[0][kb][1], f4l[0][kb][2], f4l[0][kb][3], bh0, bh1);
                    MMA16816(d0, f4h[0][kb][0], f4h[0][kb][1], f4h[0][kb][2], f4h[0][kb][3], bl0, bl1);
                }
                int c0 = nt * 8 + 2 * t;
                float oc0 = o4s[c0], oc1 = o4s[c0 + 1];
                int rows[2] = { g, g + 8 };
                float dv[2][2] = { {d0[0], d0[1]}, {d0[2], d0[3]} };
                float vm0 = 0.f, vm1 = 0.f;
#pragma unroll
                for (int r = 0; r < 2; r++) {
                    if (rows[r] < numv) {
                        int off = rows[r] * 144 + c0 * 2;
                        uint32_t hu = *(const uint32_t*)(x2hp + off);
                        uint32_t lu = *(const uint32_t*)(x2lp + off);
                        __nv_bfloat162 hb = *reinterpret_cast<__nv_bfloat162*>(&hu);
                        __nv_bfloat162 lb = *reinterpret_cast<__nv_bfloat162*>(&lu);
                        float x20 = __bfloat162float(hb.x) + __bfloat162float(lb.x);
                        float x21 = __bfloat162float(hb.y) + __bfloat162float(lb.y);
                        vm0 = fmaxf(vm0, mish(dv[r][0] + oc0) + x20);
                        vm1 = fmaxf(vm1, mish(dv[r][1] + oc1) + x21);
                    }
                }
#pragma unroll
                for (int o = 4; o <= 16; o <<= 1) {
                    vm0 = fmaxf(vm0, __shfl_xor_sync(~0u, vm0, o));
                    vm1 = fmaxf(vm1, __shfl_xor_sync(~0u, vm1, o));
                }
                if (lane < 4) {
                    g_voxelwise[(size_t)v * 64 + nt * 8 + 2 * lane]     = vm0;
                    g_voxelwise[(size_t)v * 64 + nt * 8 + 2 * lane + 1] = vm1;
                }
            }
        }
        __syncwarp();
    }
}

// ---------------- grouping ----------------
__global__ void k_count(const int* __restrict__ coors) {
    int i = blockIdx.x * blockDim.x + threadIdx.x;
    if (i >= NVOX) return;
    int cell = coors[2 * i] * BEVW + coors[2 * i + 1];
    int p = atomicAdd(&g_cellCount[cell], 1);
    if (p < CAP) g_cellMem[cell * CAP + p] = i;
}
__global__ void k_build() {
    int c = blockIdx.x * blockDim.x + threadIdx.x;
    if (c >= NCELL) return;
    int cnt = g_cellCount[c];
    if (cnt == 0) return;
    int m = min(cnt, CAP);
    int buf[CAP];
    for (int j = 0; j < m; j++) buf[j] = g_cellMem[c * CAP + j];
    for (int a = 1; a < m; a++) {
        int key = buf[a];
        int b = a - 1;
        while (b >= 0 && buf[b] > key) { buf[b + 1] = buf[b]; b--; }
        buf[b + 1] = key;
    }
    int w = atomicAdd(&g_workCount, 1);
    g_workCell[w] = c;
    int nv = min(cnt, 16);
    g_workNumv[w] = nv;
    for (int s = 0; s < 16; s++) g_workMem[w * 16 + s] = (s < nv) ? buf[s] : -1;
}

// ---------------- BFE via mma.sync (unchanged from 665us best) ----------------
#define PB    272
#define BW3H  0
#define BW3L  34816
#define BX0   69632
#define BYS   88064
#define BX17H 97280
#define BX17L 101632
#define BO3   105984
#define BMETA 106496
#define BFE_SMEM (BMETA + 1024 + 64 + 64)

__global__ __launch_bounds__(256, 2) void k_bfe(
    float* __restrict__ out,
    const float* __restrict__ W1, const float* __restrict__ bn1,
    const float* __restrict__ W2, const float* __restrict__ bn2,
    const float* __restrict__ W3, const float* __restrict__ bn3)
{
    extern __shared__ char smc[];
    const uint32_t sb = smem_u32(smc);
    float* x0s = (float*)(smc + BX0);
    float* ys  = (float*)(smc + BYS);
    float* o3s = (float*)(smc + BO3);
    int* memS    = (int*)(smc + BMETA);
    int* outIdxS = memS + 256;
    int* nvS     = outIdxS + 16;

    const int tid = threadIdx.x;
    const int wid = tid >> 5;
    const int lane = tid & 31;

    {
        int c = tid >> 1, k0 = (tid & 1) * 64;
        float s3c = bn3[c] * rsqrtf(bn3[384 + c] + EPSF);
        if (tid < 128) o3s[tid] = bn3[128 + tid] - bn3[256 + tid] *
                                  (bn3[tid] * rsqrtf(bn3[384 + tid] + EPSF));
        for (int k = k0; k < k0 + 64; k++) {
            int off = c * PB + k * 2;
            float w = W3[c * 128 + k] * s3c;
            __nv_bfloat16 h = __float2bfloat16(w);
            *(__nv_bfloat16*)(smc + BW3H + off) = h;
            *(__nv_bfloat16*)(smc + BW3L + off) = __float2bfloat16(w - __bfloat162float(h));
        }
    }

    const int g1 = tid >> 4, q1 = tid & 15;
    ull w1p[8];
#pragma unroll
    for (int k = 0; k < 4; k++) {
        ulonglong2 u = ((const ulonglong2*)(W1 + g1 * 256 + q1 * 16))[k];
        w1p[2*k] = u.x; w1p[2*k+1] = u.y;
    }
    const float s1 = bn1[g1*64 + q1]      * rsqrtf(bn1[g1*64 + 48 + q1] + EPSF);
    const float o1 = bn1[g1*64 + 16 + q1] - bn1[g1*64 + 32 + q1] * s1;

    const int o2i = tid & 127, b0 = tid >> 7;
    const int iB = o2i >> 5, gB = (o2i >> 1) & 15, cB = o2i & 1;
    ull w2p[8];
#pragma unroll
    for (int k = 0; k < 4; k++) {
        ulonglong2 u = ((const ulonglong2*)(W2 + gB * 32 + cB * 16))[k];
        w2p[2*k] = u.x; w2p[2*k+1] = u.y;
    }
    const float s2 = bn2[gB*8 + cB]     * rsqrtf(bn2[gB*8 + 6 + cB] + EPSF);
    const float o2 = bn2[gB*8 + 2 + cB] - bn2[gB*8 + 4 + cB] * s2;

    const uint32_t a_ro = (uint32_t)(lane & 15) * PB + ((lane & 16) ? 16u : 0u);
    const uint32_t b_ro = (uint32_t)(lane & 7) * PB + ((lane & 8) ? 16u : 0u);
    const int g = lane >> 2, t = lane & 3;
    __syncthreads();

    const int M = g_workCount;
    const int nb = (M + 15) >> 4;
    for (int batch = blockIdx.x; batch < nb; batch += gridDim.x) {
        if (tid < 16) {
            int w = batch * 16 + tid;
            bool ok = w < M;
            nvS[tid] = ok ? g_workNumv[w] : 0;
            int cell = ok ? g_workCell[w] : -1;
            int cy = cell / BEVW;
            int cx = cell - cy * BEVW;
            outIdxS[tid] = (cell >= 0) ? (cx * BEVH + cy) : -1;
        }
        {
            int w16 = batch * 16 + (tid >> 4);
            memS[tid] = (w16 < M) ? g_workMem[w16 * 16 + (tid & 15)] : -1;
        }
        __syncthreads();

        auto gather = [&](int s, int buf) {
#pragma unroll
            for (int i = 0; i < 8; i++) {
                int idx = tid + i * 256;
                int c = idx & 63, p = (idx >> 6) & 15, l = idx >> 10;
                int mm = memS[(s * 2 + l) * 16 + p];
                x0s[buf * 2304 + l * 1152 + c * 18 + p] =
                    (mm >= 0) ? g_voxelwise[mm * 64 + c] : 0.f;
            }
        };

        gather(0, 0);
        __syncthreads();

        for (int s = 0; s < 8; s++) {
            const int cur = s & 1;
            if (s < 7) gather(s + 1, cur ^ 1);
#pragma unroll
            for (int l = 0; l < 2; l++) {
                const int nv = nvS[s * 2 + l];
                const float* x0b = x0s + cur * 2304 + l * 1152;
                float* yb = ys + l * 1152;
#pragma unroll
                for (int i = 0; i < 4; i++) {
                    const float* row = x0b + (g1 * 4 + i) * 18;
                    ull acc = 0ull;
#pragma unroll
                    for (int kk = 0; kk < 8; kk++)
                        acc = ffma2(*(const ull*)(row + 2 * kk), w1p[kk], acc);
                    float yv = mish(fmaf(hsum(acc), s1, o1));
                    yb[(g1 * 4 + i) * 18 + q1] = (q1 < nv) ? yv : 0.f;
                }
            }
            __syncthreads();
            {
                const float* row = ys + b0 * 1152 + (gB * 4 + iB) * 18;
                ull acc = 0ull;
#pragma unroll
                for (int kk = 0; kk < 8; kk++)
                    acc = ffma2(*(const ull*)(row + 2 * kk), w2p[kk], acc);
                float x17 = mish(fmaf(hsum(acc), s2, o2));
                __nv_bfloat16 h = __float2bfloat16(x17);
                __nv_bfloat16 lo = __float2bfloat16(x17 - __bfloat162float(h));
                int off = (s * 2 + b0) * PB + o2i * 2;
                *(__nv_bfloat16*)(smc + BX17H + off) = h;
                *(__nv_bfloat16*)(smc + BX17L + off) = lo;
            }
            __syncthreads();
        }

        {
            float d[2][4] = {{0,0,0,0},{0,0,0,0}};
#pragma unroll
            for (int kb = 0; kb < 8; kb++) {
                uint32_t ah0, ah1, ah2, ah3, al0, al1, al2, al3;
                uint32_t ad = (uint32_t)(kb * 32) + a_ro;
                LDM_X4(ah0, ah1, ah2, ah3, sb + BX17H + ad);
                LDM_X4(al0, al1, al2, al3, sb + BX17L + ad);
#pragma unroll
                for (int ni = 0; ni < 2; ni++) {
                    uint32_t bd = (uint32_t)((wid * 2 + ni) * 8 * PB + kb * 32) + b_ro;
                    uint32_t bh0, bh1, bl0, bl1;
                    LDM_X2(bh0, bh1, sb + BW3H + bd);
                    LDM_X2(bl0, bl1, sb + BW3L + bd);
                    MMA16816(d[ni], ah0, ah1, ah2, ah3, bh0, bh1);
                    MMA16816(d[ni], al0, al1, al2, al3, bh0, bh1);
                    MMA16816(d[ni], ah0, ah1, ah2, ah3, bl0, bl1);
                }
            }
            __syncthreads();
#pragma unroll
            for (int ni = 0; ni < 2; ni++) {
                int c0 = (wid * 2 + ni) * 8 + 2 * t;
                float oc0 = o3s[c0], oc1 = o3s[c0 + 1];
                uint32_t hu, lu;
                bfsplit(mish(d[ni][0] + oc0), mish(d[ni][1] + oc1), hu, lu);
                *(uint32_t*)(smc + BX17H + g * PB + c0 * 2) = hu;
                *(uint32_t*)(smc + BX17L + g * PB + c0 * 2) = lu;
                bfsplit(mish(d[ni][2] + oc0), mish(d[ni][3] + oc1), hu, lu);
                *(uint32_t*)(smc + BX17H + (g + 8) * PB + c0 * 2) = hu;
                *(uint32_t*)(smc + BX17L + (g + 8) * PB + c0 * 2) = lu;
            }
        }
        __syncthreads();

        {
            float d[2][4] = {{0,0,0,0},{0,0,0,0}};
#pragma unroll
            for (int kb = 0; kb < 8; kb++) {
                uint32_t ah0, ah1, ah2, ah3, al0, al1, al2, al3;
                uint32_t ad = (uint32_t)(kb * 32) + a_ro;
                LDM_X4(ah0, ah1, ah2, ah3, sb + BX17H + ad);
                LDM_X4(al0, al1, al2, al3, sb + BX17L + ad);
#pragma unroll
                for (int ni = 0; ni < 2; ni++) {
                    uint32_t bd = (uint32_t)((wid * 2 + ni) * 8 * PB + kb * 32) + b_ro;
                    uint32_t bh0, bh1, bl0, bl1;
                    LDM_X2(bh0, bh1, sb + BW3H + bd);
                    LDM_X2(bl0, bl1, sb + BW3L + bd);
                    MMA16816(d[ni], ah0, ah1, ah2, ah3, bh0, bh1);
                    MMA16816(d[ni], al0, al1, al2, al3, bh0, bh1);
                    MMA16816(d[ni], ah0, ah1, ah2, ah3, bl0, bl1);
                }
            }
            int oi0 = outIdxS[g], oi1 = outIdxS[g + 8];
#pragma unroll
            for (int ni = 0; ni < 2; ni++) {
                int c0 = (wid * 2 + ni) * 8 + 2 * t;
                float oc0 = o3s[c0], oc1 = o3s[c0 + 1];
                if (oi0 >= 0) {
                    out[(size_t)c0 * NCELL + oi0]       = mish(d[ni][0] + oc0);
                    out[(size_t)(c0 + 1) * NCELL + oi0] = mish(d[ni][1] + oc1);
                }
                if (oi1 >= 0) {
                    out[(size_t)c0 * NCELL + oi1]       = mish(d[ni][2] + oc0);
                    out[(size_t)(c0 + 1) * NCELL + oi1] = mish(d[ni][3] + oc1);
                }
            }
        }
        __syncthreads();
    }
}

// ---------------- launcher ----------------
extern "C" void kernel_launch(void* const* d_in, const int* in_sizes, int n_in,
                              void* d_out, int out_size) {
    const float* feat   = (const float*)d_in[0];
    const int*   coors  = (const int*)d_in[1];
    const int*   nvox   = (const int*)d_in[2];
    const float* vfe1_W = (const float*)d_in[3];
    const float* vfe1_b = (const float*)d_in[4];
    const float* vfe2_W = (const float*)d_in[5];
    const float* vfe2_b = (const float*)d_in[6];
    const float* vfe3_W = (const float*)d_in[7];
    const float* vfe3_b = (const float*)d_in[8];
    const float* vfe4_W = (const float*)d_in[9];
    const float* vfe4_b = (const float*)d_in[10];
    const float* bfe1_W = (const float*)d_in[11];
    const float* bfe1_b = (const float*)d_in[12];
    const float* bfe2_W = (const float*)d_in[13];
    const float* bfe2_b = (const float*)d_in[14];
    const float* bfe3_W = (const float*)d_in[15];
    const float* bfe3_b = (const float*)d_in[16];
    float* out = (float*)d_out;

    cudaFuncSetAttribute(k_vfe, cudaFuncAttributeMaxDynamicSharedMemorySize, VFE_SMEM);
    cudaFuncSetAttribute(k_bfe, cudaFuncAttributeMaxDynamicSharedMemorySize, BFE_SMEM);

    k_zero_meta<<<(NCELL + 255) / 256, 256>>>();
    k_count<<<(NVOX + 255) / 256, 256>>>(coors);
    k_build<<<(NCELL + 255) / 256, 256>>>();
    k_vfe<<<148, 32 * NW, VFE_SMEM>>>(feat, nvox, vfe1_W, vfe1_b, vfe2_W, vfe2_b,
                                      vfe3_W, vfe3_b, vfe4_W, vfe4_b);
    k_zero_out<<<4096, 256>>>((float4*)d_out, out_size / 4);
    k_bfe<<<296, 256, BFE_SMEM>>>(out, bfe1_W, bfe1_b, bfe2_W, bfe2_b,
                                  bfe3_W, bfe3_b);
}

// round 17
// speedup vs baseline: 1.3481x; 1.3481x over previous
#include <cuda_runtime.h>
#include <cuda_bf16.h>
#include <cstdint>

#define NVOX  40000
#define BEVH  496
#define BEVW  432
#define NCELL (BEVH*BEVW)
#define CAP   32
#define EPSF  1e-5f

typedef unsigned long long ull;

__device__ float g_voxelwise[NVOX * 64];
__device__ int   g_cellCount[NCELL];
__device__ int   g_cellMem[NCELL * CAP];
__device__ int   g_workCell[NVOX];
__device__ int   g_workNumv[NVOX];
__device__ int   g_workMem[NVOX * 16];
__device__ int   g_workCount;

__device__ __forceinline__ ull pk(float x, float y) {
    ull r; asm("mov.b64 %0,{%1,%2};" : "=l"(r) : "f"(x), "f"(y)); return r;
}
__device__ __forceinline__ float hsum(ull v) {
    float a, b; asm("mov.b64 {%0,%1},%2;" : "=f"(a), "=f"(b) : "l"(v)); return a + b;
}
__device__ __forceinline__ ull ffma2(ull a, ull b, ull c) {
    ull d; asm("fma.rn.f32x2 %0,%1,%2,%3;" : "=l"(d) : "l"(a), "l"(b), "l"(c)); return d;
}
__device__ __forceinline__ float mish(float y) {
    float u = __expf(fminf(y, 25.0f));
    float t = 1.0f + u;
    t = t * t;
    return y * __fdividef(t - 1.0f, t + 1.0f);
}
__device__ __forceinline__ uint32_t smem_u32(const void* p) {
    uint32_t a;
    asm("{ .reg .u64 t; cvta.to.shared.u64 t, %1; cvt.u32.u64 %0, t; }" : "=r"(a) : "l"(p));
    return a;
}
// fast hi/lo bf16 split (bit-exact vs float2bfloat16 path)
__device__ __forceinline__ void bfsplit(float x0, float x1, uint32_t& hu, uint32_t& lu) {
    uint32_t h;
    asm("cvt.rn.bf16x2.f32 %0, %1, %2;" : "=r"(h) : "f"(x1), "f"(x0));
    float h0 = __uint_as_float(h << 16);
    float h1 = __uint_as_float(h & 0xFFFF0000u);
    float r0 = x0 - h0, r1 = x1 - h1;
    asm("cvt.rn.bf16x2.f32 %0, %1, %2;" : "=r"(lu) : "f"(r1), "f"(r0));
    hu = h;
}

#define LDM_X4(r0, r1, r2, r3, addr) \
    asm volatile("ldmatrix.sync.aligned.m8n8.x4.shared.b16 {%0,%1,%2,%3}, [%4];" \
        : "=r"(r0), "=r"(r1), "=r"(r2), "=r"(r3) : "r"(addr))
#define LDM_X2(r0, r1, addr) \
    asm volatile("ldmatrix.sync.aligned.m8n8.x2.shared.b16 {%0,%1}, [%2];" \
        : "=r"(r0), "=r"(r1) : "r"(addr))
#define MMA16816(d, a0, a1, a2, a3, b0, b1) \
    asm volatile("mma.sync.aligned.m16n8k16.row.col.f32.bf16.bf16.f32 " \
        "{%0,%1,%2,%3},{%4,%5,%6,%7},{%8,%9},{%0,%1,%2,%3};" \
        : "+f"(d[0]), "+f"(d[1]), "+f"(d[2]), "+f"(d[3]) \
        : "r"(a0), "r"(a1), "r"(a2), "r"(a3), "r"(b0), "r"(b1))

__global__ void k_zero_out(float4* out, int n4) {
    int i = blockIdx.x * blockDim.x + threadIdx.x;
    int stride = gridDim.x * blockDim.x;
    float4 z = make_float4(0.f, 0.f, 0.f, 0.f);
    for (; i < n4; i += stride) out[i] = z;
}
__global__ void k_zero_meta() {
    int i = blockIdx.x * blockDim.x + threadIdx.x;
    if (i < NCELL) g_cellCount[i] = 0;
    if (i == 0) g_workCount = 0;
}

// ---------------- VFE via mma.sync: warp = voxel, 16 warps/CTA ----------------
#define SM_W1   0
#define SM_S1   256
#define SM_O1   288
#define SM_S2   320
#define SM_O2   448
#define SM_O3   576
#define SM_O4   832
#define SM_W2   1088
#define SM_W3H  3136
#define SM_W3L  12352
#define SM_W4H  21568
#define SM_W4L  30784
#define SM_A    40000
#define AWARP   9216
#define NW      16
#define VFE_SMEM (SM_A + NW * AWARP)   /* 187456 B */
#define NTILE   ((NVOX + NW - 1) / NW)

__global__ __launch_bounds__(32 * NW) void k_vfe(
    const float* __restrict__ feat, const int* __restrict__ nvox,
    const float* __restrict__ W1, const float* __restrict__ bn1,
    const float* __restrict__ W2, const float* __restrict__ bn2,
    const float* __restrict__ W3, const float* __restrict__ bn3,
    const float* __restrict__ W4, const float* __restrict__ bn4)
{
    extern __shared__ char smc[];
    const uint32_t sb = smem_u32(smc);
    float* W1s = (float*)(smc + SM_W1);
    float* s1s = (float*)(smc + SM_S1);
    float* o1s = (float*)(smc + SM_O1);
    float* s2s = (float*)(smc + SM_S2);
    float* o2s = (float*)(smc + SM_O2);
    float* o3s = (float*)(smc + SM_O3);
    float* o4s = (float*)(smc + SM_O4);
    float* W2s = (float*)(smc + SM_W2);

    const int tid = threadIdx.x;
    const int wid = tid >> 5;
    const int lane = tid & 31;

    if (tid < 64) W1s[tid] = W1[tid];
    if (tid < 8) {
        float s = bn1[tid] * rsqrtf(bn1[24 + tid] + EPSF);
        s1s[tid] = s;
        o1s[tid] = bn1[8 + tid] - bn1[16 + tid] * s;
    }
    if (tid < 32) {
        float s = bn2[tid] * rsqrtf(bn2[96 + tid] + EPSF);
        s2s[tid] = s;
        o2s[tid] = bn2[32 + tid] - bn2[64 + tid] * s;
    }
    if (tid < 64) {
        float s3 = bn3[tid] * rsqrtf(bn3[192 + tid] + EPSF);
        o3s[tid] = bn3[64 + tid] - bn3[128 + tid] * s3;
        float s4 = bn4[tid] * rsqrtf(bn4[192 + tid] + EPSF);
        o4s[tid] = bn4[64 + tid] - bn4[128 + tid] * s4;
    }
    for (int i = tid; i < 512; i += 32 * NW) W2s[i] = W2[i];
    if (tid < 128) {
        int c = tid & 63, k0 = (tid >> 6) * 32;
        float s3c = bn3[c] * rsqrtf(bn3[192 + c] + EPSF);
        float s4c = bn4[c] * rsqrtf(bn4[192 + c] + EPSF);
        for (int k = k0; k < k0 + 32; k++) {
            int off = c * 144 + k * 2;
            float w3 = W3[c * 64 + k] * s3c;
            __nv_bfloat16 h = __float2bfloat16(w3);
            *(__nv_bfloat16*)(smc + SM_W3H + off) = h;
            *(__nv_bfloat16*)(smc + SM_W3L + off) = __float2bfloat16(w3 - __bfloat162float(h));
            float w4 = W4[c * 64 + k] * s4c;
            __nv_bfloat16 h4 = __float2bfloat16(w4);
            *(__nv_bfloat16*)(smc + SM_W4H + off) = h4;
            *(__nv_bfloat16*)(smc + SM_W4L + off) = __float2bfloat16(w4 - __bfloat162float(h4));
        }
    }
    __syncthreads();

    const uint32_t x2hA = sb + SM_A + wid * AWARP;
    const uint32_t x2lA = x2hA + 4608;
    char* const x2hp = smc + (x2hA - sb);
    char* const x2lp = smc + (x2lA - sb);
    const uint32_t a_ro = (uint32_t)(lane & 15) * 144 + ((lane & 16) ? 16u : 0u);
    const uint32_t b_ro = (uint32_t)(lane & 7) * 144 + ((lane & 8) ? 16u : 0u);
    const int g = lane >> 2, t = lane & 3;

    for (int q = blockIdx.x; q < NTILE; q += gridDim.x) {
        const int v = q * NW + wid;
        if (v >= NVOX) continue;
        const int numv = __ldg(nvox + v);
        const bool valid = lane < numv;

        float p1[8];
        {
            const float4* fv = (const float4*)(feat + (size_t)v * 256);
            float4 fa = __ldg(fv + lane * 2), fb = __ldg(fv + lane * 2 + 1);
            ull fx[4] = { pk(fa.x, fa.y), pk(fa.z, fa.w), pk(fb.x, fb.y), pk(fb.z, fb.w) };
#pragma unroll
            for (int c = 0; c < 8; c++) {
                const ull* wr = (const ull*)(W1s + c * 8);
                ull acc = ffma2(fx[0], wr[0], 0ull);
                acc = ffma2(fx[1], wr[1], acc);
                acc = ffma2(fx[2], wr[2], acc);
                acc = ffma2(fx[3], wr[3], acc);
                p1[c] = mish(fmaf(hsum(acc), s1s[c], o1s[c]));
            }
        }
        float ag[8];
#pragma unroll
        for (int c = 0; c < 8; c++) {
            float a = p1[c];
#pragma unroll
            for (int o = 16; o; o >>= 1) a = fmaxf(a, __shfl_xor_sync(~0u, a, o));
            ag[c] = a;
        }

        float p2[32];
        {
            ull xp[8];
#pragma unroll
            for (int i = 0; i < 4; i++) xp[i] = pk(p1[2*i], p1[2*i+1]);
#pragma unroll
            for (int i = 0; i < 4; i++) xp[4+i] = pk(ag[2*i], ag[2*i+1]);
#pragma unroll
            for (int c = 0; c < 32; c++) {
                const ull* wr = (const ull*)(W2s + c * 16);
                ull acc = ffma2(xp[0], wr[0], 0ull);
#pragma unroll
                for (int i = 1; i < 8; i++) acc = ffma2(xp[i], wr[i], acc);
                p2[c] = mish(fmaf(hsum(acc), s2s[c], o2s[c]));
            }
        }
        float a2[32];
#pragma unroll
        for (int c = 0; c < 32; c++) a2[c] = p2[c];
#pragma unroll
        for (int o = 16; o; o >>= 1)
#pragma unroll
            for (int c = 0; c < 32; c++) a2[c] = fmaxf(a2[c], __shfl_xor_sync(~0u, a2[c], o));

        {
            const float mv = valid ? 1.f : 0.f;
            char* rh = x2hp + lane * 144;
            char* rl = x2lp + lane * 144;
#pragma unroll
            for (int i = 0; i < 4; i++) {
                uint4 uh, ul;
                bfsplit(p2[8*i]*mv,   p2[8*i+1]*mv, uh.x, ul.x);
                bfsplit(p2[8*i+2]*mv, p2[8*i+3]*mv, uh.y, ul.y);
                bfsplit(p2[8*i+4]*mv, p2[8*i+5]*mv, uh.z, ul.z);
                bfsplit(p2[8*i+6]*mv, p2[8*i+7]*mv, uh.w, ul.w);
                *(uint4*)(rh + 16*i) = uh;
                *(uint4*)(rl + 16*i) = ul;
            }
#pragma unroll
            for (int i = 0; i < 4; i++) {
                uint4 uh, ul;
                bfsplit(a2[8*i]*mv,   a2[8*i+1]*mv, uh.x, ul.x);
                bfsplit(a2[8*i+2]*mv, a2[8*i+3]*mv, uh.y, ul.y);
                bfsplit(a2[8*i+4]*mv, a2[8*i+5]*mv, uh.z, ul.z);
                bfsplit(a2[8*i+6]*mv, a2[8*i+7]*mv, uh.w, ul.w);
                *(uint4*)(rh + 64 + 16*i) = uh;
                *(uint4*)(rl + 64 + 16*i) = ul;
            }
        }
        __syncwarp();

        uint32_t f4h[2][4][4], f4l[2][4][4];
#pragma unroll
        for (int mt = 0; mt < 2; mt++) {
            uint32_t fah[4][4], fal[4][4];
#pragma unroll
            for (int kb = 0; kb < 4; kb++) {
                uint32_t ad = (uint32_t)(mt * 16 * 144 + kb * 32) + a_ro;
                LDM_X4(fah[kb][0], fah[kb][1], fah[kb][2], fah[kb][3], x2hA + ad);
                LDM_X4(fal[kb][0], fal[kb][1], fal[kb][2], fal[kb][3], x2lA + ad);
            }
            const int r0 = mt * 16 + g, r1 = r0 + 8;
            const bool va0 = r0 < numv, va1 = r1 < numv;
#pragma unroll
            for (int nt = 0; nt < 8; nt++) {
                float d[4] = {0, 0, 0, 0};
#pragma unroll
                for (int kb = 0; kb < 4; kb++) {
                    uint32_t bd = (uint32_t)(nt * 8 * 144 + kb * 32) + b_ro;
                    uint32_t bh0, bh1, bl0, bl1;
                    LDM_X2(bh0, bh1, sb + SM_W3H + bd);
                    LDM_X2(bl0, bl1, sb + SM_W3L + bd);
                    MMA16816(d, fah[kb][0], fah[kb][1], fah[kb][2], fah[kb][3], bh0, bh1);
                    MMA16816(d, fal[kb][0], fal[kb][1], fal[kb][2], fal[kb][3], bh0, bh1);
                    MMA16816(d, fah[kb][0], fah[kb][1], fah[kb][2], fah[kb][3], bl0, bl1);
                }
                int c0 = nt * 8 + 2 * t;
                float oc0 = o3s[c0], oc1 = o3s[c0 + 1];
                int kb4 = nt >> 1, ai = (nt & 1) * 2;
                float y00 = va0 ? mish(d[0] + oc0) : 0.f;
                float y01 = va0 ? mish(d[1] + oc1) : 0.f;
                bfsplit(y00, y01, f4h[mt][kb4][ai], f4l[mt][kb4][ai]);
                float y10 = va1 ? mish(d[2] + oc0) : 0.f;
                float y11 = va1 ? mish(d[3] + oc1) : 0.f;
                bfsplit(y10, y11, f4h[mt][kb4][ai + 1], f4l[mt][kb4][ai + 1]);
            }
        }

        {
            const float vinit = (numv == 32) ? -3.0e38f : 0.f;
#pragma unroll
            for (int nt = 0; nt < 8; nt++) {
                float d0[4] = {0,0,0,0}, d1[4] = {0,0,0,0};
#pragma unroll
                for (int kb = 0; kb < 4; kb++) {
                    uint32_t bd = (uint32_t)(nt * 8 * 144 + kb * 32) + b_ro;
                    uint32_t bh0, bh1, bl0, bl1;
                    LDM_X2(bh0, bh1, sb + SM_W4H + bd);
                    LDM_X2(bl0, bl1, sb + SM_W4L + bd);
                    MMA16816(d0, f4h[0][kb][0], f4h[0][kb][1], f4h[0][kb][2], f4h[0][kb][3], bh0, bh1);
                    MMA16816(d0, f4l[0][kb][0], f4l[0][kb][1], f4l[0][kb][2], f4l[0][kb][3], bh0, bh1);
                    MMA16816(d0, f4h[0][kb][0], f4h[0][kb][1], f4h[0][kb][2], f4h[0][kb][3], bl0, bl1);
                    MMA16816(d1, f4h[1][kb][0], f4h[1][kb][1], f4h[1][kb][2], f4h[1][kb][3], bh0, bh1);
                    MMA16816(d1, f4l[1][kb][0], f4l[1][kb][1], f4l[1][kb][2], f4l[1][kb][3], bh0, bh1);
                    MMA16816(d1, f4h[1][kb][0], f4h[1][kb][1], f4h[1][kb][2], f4h[1][kb][3], bl0, bl1);
                }
                int c0 = nt * 8 + 2 * t;
                float oc0 = o4s[c0], oc1 = o4s[c0 + 1];
                int rows[4] = { g, g + 8, g + 16, g + 24 };
                float dv[4][2] = { {d0[0], d0[1]}, {d0[2], d0[3]}, {d1[0], d1[1]}, {d1[2], d1[3]} };
                float vm0 = vinit, vm1 = vinit;
#pragma unroll
                for (int r = 0; r < 4; r++) {
                    if (rows[r] < numv) {
                        int off = rows[r] * 144 + c0 * 2;
                        uint32_t hu = *(const uint32_t*)(x2hp + off);
                        uint32_t lu = *(const uint32_t*)(x2lp + off);
                        __nv_bfloat162 hb = *reinterpret_cast<__nv_bfloat162*>(&hu);
                        __nv_bfloat162 lb = *reinterpret_cast<__nv_bfloat162*>(&lu);
                        float x20 = __bfloat162float(hb.x) + __bfloat162float(lb.x);
                        float x21 = __bfloat162float(hb.y) + __bfloat162float(lb.y);
                        vm0 = fmaxf(vm0, mish(dv[r][0] + oc0) + x20);
                        vm1 = fmaxf(vm1, mish(dv[r][1] + oc1) + x21);
                    }
                }
#pragma unroll
                for (int o = 4; o <= 16; o <<= 1) {
                    vm0 = fmaxf(vm0, __shfl_xor_sync(~0u, vm0, o));
                    vm1 = fmaxf(vm1, __shfl_xor_sync(~0u, vm1, o));
                }
                if (lane < 4) {
                    g_voxelwise[(size_t)v * 64 + nt * 8 + 2 * lane]     = vm0;
                    g_voxelwise[(size_t)v * 64 + nt * 8 + 2 * lane + 1] = vm1;
                }
            }
        }
        __syncwarp();
    }
}

// ---------------- grouping ----------------
__global__ void k_count(const int* __restrict__ coors) {
    int i = blockIdx.x * blockDim.x + threadIdx.x;
    if (i >= NVOX) return;
    int cell = coors[2 * i] * BEVW + coors[2 * i + 1];
    int p = atomicAdd(&g_cellCount[cell], 1);
    if (p < CAP) g_cellMem[cell * CAP + p] = i;
}
__global__ void k_build() {
    int c = blockIdx.x * blockDim.x + threadIdx.x;
    if (c >= NCELL) return;
    int cnt = g_cellCount[c];
    if (cnt == 0) return;
    int m = min(cnt, CAP);
    int buf[CAP];
    for (int j = 0; j < m; j++) buf[j] = g_cellMem[c * CAP + j];
    for (int a = 1; a < m; a++) {
        int key = buf[a];
        int b = a - 1;
        while (b >= 0 && buf[b] > key) { buf[b + 1] = buf[b]; b--; }
        buf[b + 1] = key;
    }
    int w = atomicAdd(&g_workCount, 1);
    g_workCell[w] = c;
    int nv = min(cnt, 16);
    g_workNumv[w] = nv;
    for (int s = 0; s < 16; s++) g_workMem[w * 16 + s] = (s < nv) ? buf[s] : -1;
}

// ---------------- BFE via mma.sync (unchanged from 665us best) ----------------
#define PB    272
#define BW3H  0
#define BW3L  34816
#define BX0   69632
#define BYS   88064
#define BX17H 97280
#define BX17L 101632
#define BO3   105984
#define BMETA 106496
#define BFE_SMEM (BMETA + 1024 + 64 + 64)

__global__ __launch_bounds__(256, 2) void k_bfe(
    float* __restrict__ out,
    const float* __restrict__ W1, const float* __restrict__ bn1,
    const float* __restrict__ W2, const float* __restrict__ bn2,
    const float* __restrict__ W3, const float* __restrict__ bn3)
{
    extern __shared__ char smc[];
    const uint32_t sb = smem_u32(smc);
    float* x0s = (float*)(smc + BX0);
    float* ys  = (float*)(smc + BYS);
    float* o3s = (float*)(smc + BO3);
    int* memS    = (int*)(smc + BMETA);
    int* outIdxS = memS + 256;
    int* nvS     = outIdxS + 16;

    const int tid = threadIdx.x;
    const int wid = tid >> 5;
    const int lane = tid & 31;

    {
        int c = tid >> 1, k0 = (tid & 1) * 64;
        float s3c = bn3[c] * rsqrtf(bn3[384 + c] + EPSF);
        if (tid < 128) o3s[tid] = bn3[128 + tid] - bn3[256 + tid] *
                                  (bn3[tid] * rsqrtf(bn3[384 + tid] + EPSF));
        for (int k = k0; k < k0 + 64; k++) {
            int off = c * PB + k * 2;
            float w = W3[c * 128 + k] * s3c;
            __nv_bfloat16 h = __float2bfloat16(w);
            *(__nv_bfloat16*)(smc + BW3H + off) = h;
            *(__nv_bfloat16*)(smc + BW3L + off) = __float2bfloat16(w - __bfloat162float(h));
        }
    }

    const int g1 = tid >> 4, q1 = tid & 15;
    ull w1p[8];
#pragma unroll
    for (int k = 0; k < 4; k++) {
        ulonglong2 u = ((const ulonglong2*)(W1 + g1 * 256 + q1 * 16))[k];
        w1p[2*k] = u.x; w1p[2*k+1] = u.y;
    }
    const float s1 = bn1[g1*64 + q1]      * rsqrtf(bn1[g1*64 + 48 + q1] + EPSF);
    const float o1 = bn1[g1*64 + 16 + q1] - bn1[g1*64 + 32 + q1] * s1;

    const int o2i = tid & 127, b0 = tid >> 7;
    const int iB = o2i >> 5, gB = (o2i >> 1) & 15, cB = o2i & 1;
    ull w2p[8];
#pragma unroll
    for (int k = 0; k < 4; k++) {
        ulonglong2 u = ((const ulonglong2*)(W2 + gB * 32 + cB * 16))[k];
        w2p[2*k] = u.x; w2p[2*k+1] = u.y;
    }
    const float s2 = bn2[gB*8 + cB]     * rsqrtf(bn2[gB*8 + 6 + cB] + EPSF);
    const float o2 = bn2[gB*8 + 2 + cB] - bn2[gB*8 + 4 + cB] * s2;

    const uint32_t a_ro = (uint32_t)(lane & 15) * PB + ((lane & 16) ? 16u : 0u);
    const uint32_t b_ro = (uint32_t)(lane & 7) * PB + ((lane & 8) ? 16u : 0u);
    const int g = lane >> 2, t = lane & 3;
    __syncthreads();

    const int M = g_workCount;
    const int nb = (M + 15) >> 4;
    for (int batch = blockIdx.x; batch < nb; batch += gridDim.x) {
        if (tid < 16) {
            int w = batch * 16 + tid;
            bool ok = w < M;
            nvS[tid] = ok ? g_workNumv[w] : 0;
            int cell = ok ? g_workCell[w] : -1;
            int cy = cell / BEVW;
            int cx = cell - cy * BEVW;
            outIdxS[tid] = (cell >= 0) ? (cx * BEVH + cy) : -1;
        }
        {
            int w16 = batch * 16 + (tid >> 4);
            memS[tid] = (w16 < M) ? g_workMem[w16 * 16 + (tid & 15)] : -1;
        }
        __syncthreads();

        auto gather = [&](int s, int buf) {
#pragma unroll
            for (int i = 0; i < 8; i++) {
                int idx = tid + i * 256;
                int c = idx & 63, p = (idx >> 6) & 15, l = idx >> 10;
                int mm = memS[(s * 2 + l) * 16 + p];
                x0s[buf * 2304 + l * 1152 + c * 18 + p] =
                    (mm >= 0) ? g_voxelwise[mm * 64 + c] : 0.f;
            }
        };

        gather(0, 0);
        __syncthreads();

        for (int s = 0; s < 8; s++) {
            const int cur = s & 1;
            if (s < 7) gather(s + 1, cur ^ 1);
#pragma unroll
            for (int l = 0; l < 2; l++) {
                const int nv = nvS[s * 2 + l];
                const float* x0b = x0s + cur * 2304 + l * 1152;
                float* yb = ys + l * 1152;
#pragma unroll
                for (int i = 0; i < 4; i++) {
                    const float* row = x0b + (g1 * 4 + i) * 18;
                    ull acc = 0ull;
#pragma unroll
                    for (int kk = 0; kk < 8; kk++)
                        acc = ffma2(*(const ull*)(row + 2 * kk), w1p[kk], acc);
                    float yv = mish(fmaf(hsum(acc), s1, o1));
                    yb[(g1 * 4 + i) * 18 + q1] = (q1 < nv) ? yv : 0.f;
                }
            }
            __syncthreads();
            {
                const float* row = ys + b0 * 1152 + (gB * 4 + iB) * 18;
                ull acc = 0ull;
#pragma unroll
                for (int kk = 0; kk < 8; kk++)
                    acc = ffma2(*(const ull*)(row + 2 * kk), w2p[kk], acc);
                float x17 = mish(fmaf(hsum(acc), s2, o2));
                uint32_t hu, lu;
                bfsplit(x17, 0.f, hu, lu);
                int off = (s * 2 + b0) * PB + o2i * 2;
                *(__nv_bfloat16*)(smc + BX17H + off) = *(__nv_bfloat16*)&hu;
                *(__nv_bfloat16*)(smc + BX17L + off) = *(__nv_bfloat16*)&lu;
            }
            __syncthreads();
        }

        {
            float d[2][4] = {{0,0,0,0},{0,0,0,0}};
#pragma unroll
            for (int kb = 0; kb < 8; kb++) {
                uint32_t ah0, ah1, ah2, ah3, al0, al1, al2, al3;
                uint32_t ad = (uint32_t)(kb * 32) + a_ro;
                LDM_X4(ah0, ah1, ah2, ah3, sb + BX17H + ad);
                LDM_X4(al0, al1, al2, al3, sb + BX17L + ad);
#pragma unroll
                for (int ni = 0; ni < 2; ni++) {
                    uint32_t bd = (uint32_t)((wid * 2 + ni) * 8 * PB + kb * 32) + b_ro;
                    uint32_t bh0, bh1, bl0, bl1;
                    LDM_X2(bh0, bh1, sb + BW3H + bd);
                    LDM_X2(bl0, bl1, sb + BW3L + bd);
                    MMA16816(d[ni], ah0, ah1, ah2, ah3, bh0, bh1);
                    MMA16816(d[ni], al0, al1, al2, al3, bh0, bh1);
                    MMA16816(d[ni], ah0, ah1, ah2, ah3, bl0, bl1);
                }
            }
            __syncthreads();
#pragma unroll
            for (int ni = 0; ni < 2; ni++) {
                int c0 = (wid * 2 + ni) * 8 + 2 * t;
                float oc0 = o3s[c0], oc1 = o3s[c0 + 1];
                uint32_t hu, lu;
                bfsplit(mish(d[ni][0] + oc0), mish(d[ni][1] + oc1), hu, lu);
                *(uint32_t*)(smc + BX17H + g * PB + c0 * 2) = hu;
                *(uint32_t*)(smc + BX17L + g * PB + c0 * 2) = lu;
                bfsplit(mish(d[ni][2] + oc0), mish(d[ni][3] + oc1), hu, lu);
                *(uint32_t*)(smc + BX17H + (g + 8) * PB + c0 * 2) = hu;
                *(uint32_t*)(smc + BX17L + (g + 8) * PB + c0 * 2) = lu;
            }
        }
        __syncthreads();

        {
            float d[2][4] = {{0,0,0,0},{0,0,0,0}};
#pragma unroll
            for (int kb = 0; kb < 8; kb++) {
                uint32_t ah0, ah1, ah2, ah3, al0, al1, al2, al3;
                uint32_t ad = (uint32_t)(kb * 32) + a_ro;
                LDM_X4(ah0, ah1, ah2, ah3, sb + BX17H + ad);
                LDM_X4(al0, al1, al2, al3, sb + BX17L + ad);
#pragma unroll
                for (int ni = 0; ni < 2; ni++) {
                    uint32_t bd = (uint32_t)((wid * 2 + ni) * 8 * PB + kb * 32) + b_ro;
                    uint32_t bh0, bh1, bl0, bl1;
                    LDM_X2(bh0, bh1, sb + BW3H + bd);
                    LDM_X2(bl0, bl1, sb + BW3L + bd);
                    MMA16816(d[ni], ah0, ah1, ah2, ah3, bh0, bh1);
                    MMA16816(d[ni], al0, al1, al2, al3, bh0, bh1);
                    MMA16816(d[ni], ah0, ah1, ah2, ah3, bl0, bl1);
                }
            }
            int oi0 = outIdxS[g], oi1 = outIdxS[g + 8];
#pragma unroll
            for (int ni = 0; ni < 2; ni++) {
                int c0 = (wid * 2 + ni) * 8 + 2 * t;
                float oc0 = o3s[c0], oc1 = o3s[c0 + 1];
                if (oi0 >= 0) {
                    out[(size_t)c0 * NCELL + oi0]       = mish(d[ni][0] + oc0);
                    out[(size_t)(c0 + 1) * NCELL + oi0] = mish(d[ni][1] + oc1);
                }
                if (oi1 >= 0) {
                    out[(size_t)c0 * NCELL + oi1]       = mish(d[ni][2] + oc0);
                    out[(size_t)(c0 + 1) * NCELL + oi1] = mish(d[ni][3] + oc1);
                }
            }
        }
        __syncthreads();
    }
}

// ---------------- launcher ----------------
extern "C" void kernel_launch(void* const* d_in, const int* in_sizes, int n_in,
                              void* d_out, int out_size) {
    const float* feat   = (const float*)d_in[0];
    const int*   coors  = (const int*)d_in[1];
    const int*   nvox   = (const int*)d_in[2];
    const float* vfe1_W = (const float*)d_in[3];
    const float* vfe1_b = (const float*)d_in[4];
    const float* vfe2_W = (const float*)d_in[5];
    const float* vfe2_b = (const float*)d_in[6];
    const float* vfe3_W = (const float*)d_in[7];
    const float* vfe3_b = (const float*)d_in[8];
    const float* vfe4_W = (const float*)d_in[9];
    const float* vfe4_b = (const float*)d_in[10];
    const float* bfe1_W = (const float*)d_in[11];
    const float* bfe1_b = (const float*)d_in[12];
    const float* bfe2_W = (const float*)d_in[13];
    const float* bfe2_b = (const float*)d_in[14];
    const float* bfe3_W = (const float*)d_in[15];
    const float* bfe3_b = (const float*)d_in[16];
    float* out = (float*)d_out;

    cudaFuncSetAttribute(k_vfe, cudaFuncAttributeMaxDynamicSharedMemorySize, VFE_SMEM);
    cudaFuncSetAttribute(k_bfe, cudaFuncAttributeMaxDynamicSharedMemorySize, BFE_SMEM);

    k_zero_meta<<<(NCELL + 255) / 256, 256>>>();
    k_count<<<(NVOX + 255) / 256, 256>>>(coors);
    k_build<<<(NCELL + 255) / 256, 256>>>();
    k_vfe<<<148, 32 * NW, VFE_SMEM>>>(feat, nvox, vfe1_W, vfe1_b, vfe2_W, vfe2_b,
                                      vfe3_W, vfe3_b, vfe4_W, vfe4_b);
    k_zero_out<<<4096, 256>>>((float4*)d_out, out_size / 4);
    k_bfe<<<296, 256, BFE_SMEM>>>(out, bfe1_W, bfe1_b, bfe2_W, bfe2_b,
                                  bfe3_W, bfe3_b);
}